// round 8
// baseline (speedup 1.0000x reference)
#include <cuda_runtime.h>
#include <cuda_bf16.h>
#include <math.h>

#define BATCH    8192
#define DLAT     512
#define NCB      2
#define KCODES   8192
#define DSUB     256

#define BM 128
#define BN 64
#define KS 32
#define KPAD (KS + 8)
#define NSTAGE 4
#define CAP 192
#define MARGIN_F 8e-5f

#define NROWS (BATCH * NCB)     // 16384

// Scratch (static device globals; no allocations)
__device__ __align__(16) __nv_bfloat16 g_zbf[BATCH * DLAT];
__device__ __align__(16) __nv_bfloat16 g_ebf[NCB * KCODES * DSUB];
__device__ uint2    g_cand[NROWS * CAP];   // {float bits of c_approx, k}
__device__ int      g_cnt[NROWS];
__device__ unsigned g_gmax[NROWS];         // sortable-encoded max c_approx
__device__ unsigned long long g_packed[NROWS];
__device__ int      g_counts[NCB * KCODES];
__device__ float    g_zsq[NROWS];
__device__ double   g_sse;

__device__ __forceinline__ unsigned f_enc(float f) {   // monotone float->uint
    unsigned b = __float_as_uint(f);
    return (b & 0x80000000u) ? ~b : (b | 0x80000000u);
}
__device__ __forceinline__ float f_dec(unsigned u) {
    return __uint_as_float((u & 0x80000000u) ? (u ^ 0x80000000u) : ~u);
}
__device__ __forceinline__ void cp16(void* s, const void* g) {
    unsigned sa = (unsigned)__cvta_generic_to_shared(s);
    asm volatile("cp.async.cg.shared.global [%0], [%1], 16;" :: "r"(sa), "l"(g));
}
#define CP_COMMIT() asm volatile("cp.async.commit_group;")
#define CP_WAIT(N)  asm volatile("cp.async.wait_group %0;" :: "n"(N))

// ---------------------------------------------------------------------------
__global__ void init_kernel() {
    int i = blockIdx.x * blockDim.x + threadIdx.x;
    if (i < NROWS) { g_cnt[i] = 0; g_gmax[i] = 0u; }
    if (i < NCB * KCODES) g_counts[i] = 0;
    if (i == 0) g_sse = 0.0;
}

// ---------------------------------------------------------------------------
__global__ void convert_kernel(const float* __restrict__ z,
                               const float* __restrict__ emb) {
    int i = blockIdx.x * blockDim.x + threadIdx.x;   // x4 vectorized
    float4 a = ((const float4*)z)[i];
    float4 b = ((const float4*)emb)[i];
    __nv_bfloat162 p0, p1, q0, q1;
    p0.x = __float2bfloat16_rn(a.x); p0.y = __float2bfloat16_rn(a.y);
    p1.x = __float2bfloat16_rn(a.z); p1.y = __float2bfloat16_rn(a.w);
    q0.x = __float2bfloat16_rn(b.x); q0.y = __float2bfloat16_rn(b.y);
    q1.x = __float2bfloat16_rn(b.z); q1.y = __float2bfloat16_rn(b.w);
    ((__nv_bfloat162*)g_zbf)[2 * i]     = p0;
    ((__nv_bfloat162*)g_zbf)[2 * i + 1] = p1;
    ((__nv_bfloat162*)g_ebf)[2 * i]     = q0;
    ((__nv_bfloat162*)g_ebf)[2 * i + 1] = q1;
}

// ---------------------------------------------------------------------------
// z_sq — numerics proven in R3; unchanged.
__global__ void zsq_kernel(const float* __restrict__ z) {
    int w    = blockIdx.x * (blockDim.x >> 5) + (threadIdx.x >> 5);
    int lane = threadIdx.x & 31;
    const float* row = z + (size_t)w * DSUB;
    float s = 0.f;
#pragma unroll
    for (int t = 0; t < DSUB / 32; t++) {
        float v  = row[lane + 32 * t];
        s = __fadd_rn(s, __fmul_rn(v, v));
    }
#pragma unroll
    for (int o = 16; o; o >>= 1)
        s = __fadd_rn(s, __shfl_down_sync(0xffffffffu, s, o));
    if (lane == 0) g_zsq[w] = s;
}

// ---------------------------------------------------------------------------
// Screening: bf16 mma.sync, warp tile 32x32 (8 warps: 4 along M, 2 along N),
// 4-stage cp.async pipeline, LDSM-hoisted fragments, 3 CTAs/SM.
__global__ __launch_bounds__(256, 3)
void screen_kernel() {
    extern __shared__ char smem[];
    // layout: As[NSTAGE][BM][KPAD] then Bs[NSTAGE][BN][KPAD] then redmax[2][BM]
    __nv_bfloat16 (*As)[BM][KPAD] = (__nv_bfloat16 (*)[BM][KPAD])smem;
    __nv_bfloat16 (*Bs)[BN][KPAD] =
        (__nv_bfloat16 (*)[BN][KPAD])(smem + NSTAGE * BM * KPAD * 2);
    float* redmax = (float*)(smem + NSTAGE * (BM + BN) * KPAD * 2);

    const int n  = blockIdx.z;
    const int bm = blockIdx.y;
    const int bn = blockIdx.x;
    const int tid  = threadIdx.x;
    const int wid  = tid >> 5;
    const int lane = tid & 31;
    const int wm = wid & 3;       // 4 warps along M (32 rows each)
    const int wn = wid >> 2;      // 2 warps along N (32 cols each)
    const int g  = lane >> 2;     // groupID
    const int t  = lane & 3;      // thread-in-group
    const int jq   = lane >> 3;   // ldmatrix quad
    const int rsub = lane & 7;

    const __nv_bfloat16* Ag = g_zbf + (size_t)(bm * BM) * DLAT + n * DSUB;
    const __nv_bfloat16* Bg = g_ebf + (size_t)n * KCODES * DSUB + (size_t)(bn * BN) * DSUB;

    float acc[2][4][4];
#pragma unroll
    for (int mt = 0; mt < 2; mt++)
#pragma unroll
        for (int nt = 0; nt < 4; nt++)
#pragma unroll
            for (int q = 0; q < 4; q++) acc[mt][nt][q] = 0.f;

    // tile loader: A = 128 rows x 4 chunks (2/thread), B = 64 rows x 4 (1/thread)
    auto loadTiles = [&](int st, int kb) {
#pragma unroll
        for (int u = 0; u < 2; u++) {
            int id = tid + u * 256;
            int row = id >> 2;
            int q = id & 3;
            cp16(&As[st][row][q * 8], Ag + (size_t)row * DLAT + kb + q * 8);
        }
        {
            int row = tid >> 2;
            int q = tid & 3;
            cp16(&Bs[st][row][q * 8], Bg + (size_t)row * DSUB + kb + q * 8);
        }
        CP_COMMIT();
    };

    loadTiles(0, 0);
    loadTiles(1, KS);
    loadTiles(2, 2 * KS);

    for (int kbi = 0; kbi < DSUB / KS; kbi++) {
        if (kbi <= 5)      CP_WAIT(2);
        else if (kbi == 6) CP_WAIT(1);
        else               CP_WAIT(0);
        __syncthreads();
        if (kbi + 3 < DSUB / KS) loadTiles((kbi + 3) & 3, (kbi + 3) * KS);

        const int st = kbi & 3;
        unsigned a[2][2][4], b[2][2][4];   // [ks][mt|np][..]
        // ---- hoisted LDSM for both 16-K halves ----
#pragma unroll
        for (int ks = 0; ks < 2; ks++) {
#pragma unroll
            for (int mt = 0; mt < 2; mt++) {
                int row = wm * 32 + mt * 16 + ((jq & 1) << 3) + rsub;
                int col = ks * 16 + ((jq >> 1) << 3);
                unsigned addr = (unsigned)__cvta_generic_to_shared(&As[st][row][col]);
                asm volatile(
                    "ldmatrix.sync.aligned.m8n8.x4.shared.b16 {%0,%1,%2,%3}, [%4];"
                    : "=r"(a[ks][mt][0]), "=r"(a[ks][mt][1]),
                      "=r"(a[ks][mt][2]), "=r"(a[ks][mt][3]) : "r"(addr));
            }
#pragma unroll
            for (int np = 0; np < 2; np++) {
                int row = wn * 32 + np * 16 + ((jq >> 1) << 3) + rsub;
                int col = ks * 16 + ((jq & 1) << 3);
                unsigned addr = (unsigned)__cvta_generic_to_shared(&Bs[st][row][col]);
                asm volatile(
                    "ldmatrix.sync.aligned.m8n8.x4.shared.b16 {%0,%1,%2,%3}, [%4];"
                    : "=r"(b[ks][np][0]), "=r"(b[ks][np][1]),
                      "=r"(b[ks][np][2]), "=r"(b[ks][np][3]) : "r"(addr));
            }
        }
        // ---- 16 MMAs ----
#pragma unroll
        for (int ks = 0; ks < 2; ks++)
#pragma unroll
            for (int mt = 0; mt < 2; mt++)
#pragma unroll
                for (int nt = 0; nt < 4; nt++) {
                    asm volatile(
                        "mma.sync.aligned.m16n8k16.row.col.f32.bf16.bf16.f32 "
                        "{%0,%1,%2,%3}, {%4,%5,%6,%7}, {%8,%9}, {%0,%1,%2,%3};"
                        : "+f"(acc[mt][nt][0]), "+f"(acc[mt][nt][1]),
                          "+f"(acc[mt][nt][2]), "+f"(acc[mt][nt][3])
                        : "r"(a[ks][mt][0]), "r"(a[ks][mt][1]),
                          "r"(a[ks][mt][2]), "r"(a[ks][mt][3]),
                          "r"(b[ks][nt >> 1][2 * (nt & 1)]),
                          "r"(b[ks][nt >> 1][2 * (nt & 1) + 1]));
                }
        __syncthreads();
    }

    // Per-row local max over this block's 64 cols, then candidate emission.
#pragma unroll
    for (int mt = 0; mt < 2; mt++) {
        float lo = -1e30f, hi = -1e30f;
#pragma unroll
        for (int nt = 0; nt < 4; nt++) {
            lo = fmaxf(lo, fmaxf(acc[mt][nt][0], acc[mt][nt][1]));
            hi = fmaxf(hi, fmaxf(acc[mt][nt][2], acc[mt][nt][3]));
        }
#pragma unroll
        for (int o = 1; o < 4; o <<= 1) {
            lo = fmaxf(lo, __shfl_xor_sync(0xffffffffu, lo, o));
            hi = fmaxf(hi, __shfl_xor_sync(0xffffffffu, hi, o));
        }
        if (t == 0) {
            redmax[wn * BM + wm * 32 + mt * 16 + g]     = lo;
            redmax[wn * BM + wm * 32 + mt * 16 + g + 8] = hi;
        }
    }
    __syncthreads();

#pragma unroll
    for (int mt = 0; mt < 2; mt++) {
#pragma unroll
        for (int half = 0; half < 2; half++) {
            int lr = wm * 32 + mt * 16 + g + 8 * half;
            float full = fmaxf(redmax[lr], redmax[BM + lr]);
            int rowid = (bm * BM + lr) * NCB + n;
            if (wn == 0 && t == 0)
                atomicMax(&g_gmax[rowid], f_enc(full));
            float thresh = full - MARGIN_F;
#pragma unroll
            for (int nt = 0; nt < 4; nt++) {
#pragma unroll
                for (int e = 0; e < 2; e++) {
                    float v = acc[mt][nt][2 * half + e];
                    if (v >= thresh) {
                        int slot = atomicAdd(&g_cnt[rowid], 1);
                        if (slot < CAP) {
                            int k = bn * BN + wn * 32 + nt * 8 + 2 * t + e;
                            g_cand[rowid * CAP + slot] =
                                make_uint2(__float_as_uint(v), (unsigned)k);
                        }
                    }
                }
            }
        }
    }
}

// ---------------------------------------------------------------------------
// Exact rescore: ascending-d single-accumulator FMA chain (R3-proven).
__global__ __launch_bounds__(256)
void rescore_kernel(const float* __restrict__ z, const float* __restrict__ emb) {
    __shared__ float sz[8][DSUB];
    int wid  = threadIdx.x >> 5;
    int lane = threadIdx.x & 31;
    int row  = blockIdx.x * 8 + wid;
    int b = row >> 1;
    int n = row & 1;

    const float* zp = z + (size_t)b * DLAT + n * DSUB;
#pragma unroll
    for (int tq = 0; tq < DSUB / 32; tq++)
        sz[wid][lane + 32 * tq] = zp[lane + 32 * tq];
    __syncwarp();

    float zsq    = g_zsq[row];
    float thresh = f_dec(g_gmax[row]) - MARGIN_F;
    int cnt = g_cnt[row]; if (cnt > CAP) cnt = CAP;

    unsigned long long key = 0xFFFFFFFFFFFFFFFFull;
    for (int c = lane; c < cnt; c += 32) {
        uint2 cd = g_cand[row * CAP + c];
        if (__uint_as_float(cd.x) < thresh) continue;
        int k = (int)cd.y;
        const float* e = emb + ((size_t)n * KCODES + k) * DSUB;
        float acc = 0.f;
#pragma unroll 8
        for (int d = 0; d < DSUB; d++)
            acc = __fmaf_rn(sz[wid][d], e[d], acc);
        float u = __fmaf_rn(-2.0f, acc, zsq);
        unsigned long long cand = ((unsigned long long)f_enc(u) << 32) | (unsigned)k;
        if (cand < key) key = cand;
    }
#pragma unroll
    for (int o = 16; o; o >>= 1) {
        unsigned long long other = __shfl_xor_sync(0xffffffffu, key, o);
        if (other < key) key = other;
    }
    if (lane == 0) g_packed[row] = key;
}

// ---------------------------------------------------------------------------
// out = RN(z + RN(z_q - z)); indices, commitment SSE, usage counts.
__global__ void gather_kernel(const float* __restrict__ z,
                              const float* __restrict__ emb,
                              float* __restrict__ out) {
    int w    = blockIdx.x * (blockDim.x >> 5) + (threadIdx.x >> 5);
    int lane = threadIdx.x & 31;
    int b = w >> 1;
    int n = w & 1;

    int idx = (int)(g_packed[w] & 0xFFFFFFFFull);

    if (lane == 0) {
        out[(size_t)BATCH * DLAT + w] = (float)idx;
        atomicAdd(&g_counts[n * KCODES + idx], 1);
    }

    const float* e  = emb + ((size_t)n * KCODES + idx) * DSUB;
    const float* zp = z   + (size_t)b * DLAT + n * DSUB;
    float*       op = out + (size_t)b * DLAT + n * DSUB;

    float s = 0.f;
#pragma unroll
    for (int t = 0; t < DSUB / 32; t++) {
        float ev = e[lane + 32 * t];
        float zv = zp[lane + 32 * t];
        float r  = __fsub_rn(ev, zv);
        op[lane + 32 * t] = __fadd_rn(zv, r);
        float d = __fsub_rn(zv, ev);
        s = __fmaf_rn(d, d, s);
    }
#pragma unroll
    for (int o = 16; o; o >>= 1) s += __shfl_down_sync(0xffffffffu, s, o);
    if (lane == 0) atomicAdd(&g_sse, (double)s);
}

// ---------------------------------------------------------------------------
__global__ void final_kernel(float* __restrict__ out) {
    __shared__ float red[256];
    int tid = threadIdx.x;
    float s = 0.f;
    for (int k = tid; k < KCODES; k += 256) {
        float p = (float)(g_counts[k] + g_counts[KCODES + k]) /
                  (float)(NCB * BATCH);
        s += p * logf(p + 1e-10f);
    }
    red[tid] = s;
    __syncthreads();
    for (int o = 128; o; o >>= 1) {
        if (tid < o) red[tid] += red[tid + o];
        __syncthreads();
    }
    if (tid == 0) {
        size_t off = (size_t)BATCH * DLAT + (size_t)NROWS;
        out[off + 0] = (float)(0.25 * (g_sse / (double)((size_t)BATCH * DLAT)));
        out[off + 1] = 0.0f;
        out[off + 2] = expf(-red[0]);
    }
}

// ---------------------------------------------------------------------------
extern "C" void kernel_launch(void* const* d_in, const int* in_sizes, int n_in,
                              void* d_out, int out_size) {
    const float* z   = (const float*)d_in[0];   // [8192, 512]
    const float* emb = (const float*)d_in[1];   // [2, 8192, 256]
    float* out = (float*)d_out;

    const int smem_bytes = NSTAGE * (BM + BN) * KPAD * 2 + 2 * BM * 4;
    cudaFuncSetAttribute(screen_kernel,
                         cudaFuncAttributeMaxDynamicSharedMemorySize, smem_bytes);

    init_kernel<<<(NROWS + 255) / 256, 256>>>();
    convert_kernel<<<(BATCH * DLAT / 4) / 256, 256>>>(z, emb);
    zsq_kernel<<<NROWS / 8, 256>>>(z);

    dim3 grid(KCODES / BN, BATCH / BM, NCB);
    screen_kernel<<<grid, 256, smem_bytes>>>();

    rescore_kernel<<<NROWS / 8, 256>>>(z, emb);
    gather_kernel<<<NROWS / 8, 256>>>(z, emb, out);
    final_kernel<<<1, 256>>>(out);
}